// round 8
// baseline (speedup 1.0000x reference)
#include <cuda_runtime.h>
#include <cuda_bf16.h>
#include <cstdint>

#define BB 256
#define VV 50
#define NNODE 32
#define DD 128
#define NDI 4096
#define HH 384
#define LL 12
#define CSS 10
#define GG 1560
#define GPAD 1792
#define GP2 2048
#define HSS 64
#define OUTT 128
#define KC2 3840
#define LDT 40

typedef __nv_bfloat16 bf;

__device__ bf g_WkH[(size_t)GPAD*NDI], g_WkL[(size_t)GPAD*NDI];
__device__ bf g_embH[10001*DD], g_embL[10001*DD];
__device__ bf g_WcH[(size_t)HH*KC2], g_WcL[(size_t)HH*KC2];
__device__ bf g_WrH[(size_t)GP2*HH], g_WrL[(size_t)GP2*HH];
__device__ bf g_hH[BB*HH], g_hL[BB*HH];
__device__ float g_bias[GG], g_WsumT[GG];
__device__ float g_XO[(size_t)VV*BB*GG];
__device__ float g_xobuf[BB*GG];
__device__ float g_c[BB*HH];
__device__ float g_hs[(size_t)VV*BB*HH];
__device__ float g_dists[VV*BB];
__device__ float g_ld[VV*BB*CSS];
__device__ float g_mh[(size_t)VV*BB*HH];
__device__ float g_hid[(size_t)VV*BB*HSS];
__device__ float g_theme[(size_t)VV*BB*HH];
__device__ float g_rnn[(size_t)BB*VV*HH];
__device__ float g_outPart[16*BB*OUTT];
__device__ unsigned g_vflag[VV];
__device__ unsigned g_themeflag;

__device__ __forceinline__ float sigmoidf(float x){ return 1.f/(1.f+expf(-x)); }
__device__ __forceinline__ void bsplit(float v, bf& hi, bf& lo){
    bf h = __float2bfloat16(v); hi = h; lo = __float2bfloat16(v - __bfloat162float(h));
}
__device__ __forceinline__ void cpa16(uint32_t dst, const void* src){
    asm volatile("cp.async.cg.shared.global [%0], [%1], 16;" :: "r"(dst), "l"(src));
}
__device__ __forceinline__ void ldsm4(unsigned* r, const bf* p){
    unsigned a = (unsigned)__cvta_generic_to_shared(p);
    asm volatile("ldmatrix.sync.aligned.m8n8.x4.shared.b16 {%0,%1,%2,%3}, [%4];"
        : "=r"(r[0]),"=r"(r[1]),"=r"(r[2]),"=r"(r[3]) : "r"(a));
}
__device__ __forceinline__ void mma16816(float* c, const unsigned* a, unsigned b0, unsigned b1){
    asm volatile("mma.sync.aligned.m16n8k16.row.col.f32.bf16.bf16.f32 "
        "{%0,%1,%2,%3}, {%4,%5,%6,%7}, {%8,%9}, {%0,%1,%2,%3};"
        : "+f"(c[0]),"+f"(c[1]),"+f"(c[2]),"+f"(c[3])
        : "r"(a[0]),"r"(a[1]),"r"(a[2]),"r"(a[3]), "r"(b0),"r"(b1));
}

// ---------------- prep ----------------
__global__ void k_prep(const float* __restrict__ kw, const float* __restrict__ rw,
                       const float* __restrict__ cw, const float* __restrict__ kb,
                       const float* __restrict__ rb, const float* __restrict__ em)
{
    const long R1=(long)GPAD*NDI, R2=10001L*DD, R3=(long)HH*KC2, R4=GG, R5=(long)GP2*HH, R6=(long)BB*HH;
    long i = (long)blockIdx.x*256 + threadIdx.x;
    if (i < R1){ long g=i/NDI,k=i%NDI; float v=(g<GG)?kw[g*4097+k]:0.f; bsplit(v,g_WkH[i],g_WkL[i]); return; }
    i-=R1;
    if (i < R2){ bsplit(em[i],g_embH[i],g_embL[i]); return; }
    i-=R2;
    if (i < R3){ long o=i/KC2, c=i%KC2; long k=c/HH, h=c%HH;
        bsplit(cw[(o*HH+h)*CSS+k], g_WcH[i], g_WcL[i]); return; }
    i-=R3;
    if (i < R4){ g_bias[i]=kb[i]+rb[i]; g_WsumT[i]=kw[i*4097+4096]+rw[i*385+384]; return; }
    i-=R4;
    if (i < R5){ long g=i/HH,j=i%HH; float v=(g<GG)? rw[g*385+j] : 0.f;
        bsplit(v, g_WrH[i], g_WrL[i]); return; }
    i-=R5;
    if (i < R6){ g_c[i]=0.f; g_hH[i]=__float2bfloat16(0.f); g_hL[i]=__float2bfloat16(0.f); return; }
    i-=R6;
    if (i < VV+1){ if (i<VV) g_vflag[i]=0u; else g_themeflag=0u; }
}

// -------- mma.sync split-3 bf16 GEMM: C(128x128) = A(128xK) * B(128xK)^T --------
// MODE 0: A = gathered embeddings (m = v*256+b, V-MAJOR), B = Wk, K=4096, epi -> g_XO + v-flag
// MODE 1: A = ld*hs built on the fly (m=t*256+b), B = Wc, K=3840, epi waits themeflag -> g_rnn
template<int MODE>
__global__ void __launch_bounds__(256,2) k_gma(const int* __restrict__ ids,
    const float* __restrict__ tv, const float* __restrict__ cb)
{
    extern __shared__ __align__(16) bf smem[];
    bf* AsH = smem;
    bf* AsL = AsH + 2*128*LDT;
    bf* BsH = AsL + 2*128*LDT;
    bf* BsL = BsH + 2*128*LDT;
    uint32_t sAH = (uint32_t)__cvta_generic_to_shared(AsH);
    uint32_t sAL = (uint32_t)__cvta_generic_to_shared(AsL);
    uint32_t sBH = (uint32_t)__cvta_generic_to_shared(BsH);
    uint32_t sBL = (uint32_t)__cvta_generic_to_shared(BsL);
    const int tid = threadIdx.x, lane = tid&31, w = tid>>5;
    const int wm = w>>2, wn = w&3;
    const int m0 = blockIdx.y*128, n0 = blockIdx.x*128;
    const int KCH = (MODE==0)? NDI/32 : KC2/32;

    float c[4][4][4];
#pragma unroll
    for(int a=0;a<4;a++)
#pragma unroll
        for(int b=0;b<4;b++)
#pragma unroll
            for(int q=0;q<4;q++) c[a][b][q]=0.f;

    auto loadB = [&](int ci, int buf){
        int k0 = ci*32;
        for (int s=tid; s<1024; s+=256){
            int hl = s>>9, r = (s>>2)&127, seg = s&3;
            uint32_t dst = (hl? sBL : sBH) + ((buf*128+r)*LDT + seg*8)*2;
            const bf* src = (MODE==0)
                ? ((hl? g_WkL : g_WkH) + (size_t)(n0+r)*NDI + k0 + seg*8)
                : ((hl? g_WcL : g_WcH) + (size_t)(n0+r)*KC2 + k0 + seg*8);
            cpa16(dst, src);
        }
    };
    auto loadA0 = [&](int ci, int buf){
        int k0 = ci*32;
        for (int s=tid; s<1024; s+=256){
            int hl = s>>9, r = (s>>2)&127, seg = s&3;
            uint32_t dst = (hl? sAL : sAH) + ((buf*128+r)*LDT + seg*8)*2;
            int m = m0 + r;                      // v-major: m = v*256 + b
            int b = m & 255, v = m >> 8;
            int id = ids[b*(VV*NNODE) + v*NNODE + (k0>>7)];
            const bf* src = (hl? g_embL : g_embH) + (size_t)id*DD + (k0&127) + seg*8;
            cpa16(dst, src);
        }
    };
    float4 ra[4]; float rl = 0.f;
    auto loadA1 = [&](int ci){
        int k0 = ci*32;
        int k = k0/384, hb = k0 - k*384;
        int m = m0 + (tid>>1);
        int t = m>>8, b = m&255;
        int s = t - (CSS-1) + k;
        if (s >= 0){
            rl = g_ld[(size_t)m*CSS + k];
            const float4* src = reinterpret_cast<const float4*>(
                g_hs + ((size_t)s*BB + b)*HH + hb + (tid&1)*16);
#pragma unroll
            for(int q=0;q<4;q++) ra[q] = src[q];
        } else {
            rl = 0.f;
#pragma unroll
            for(int q=0;q<4;q++) ra[q] = make_float4(0.f,0.f,0.f,0.f);
        }
    };
    auto storeA1 = [&](int buf){
        int r = tid>>1, hf = tid&1;
        unsigned ph[8], pl[8];
        const float* f = reinterpret_cast<const float*>(ra);
#pragma unroll
        for(int q=0;q<8;q++){
            bf h0,l0,h1,l1;
            bsplit(f[2*q+0]*rl, h0, l0);
            bsplit(f[2*q+1]*rl, h1, l1);
            ph[q] = (unsigned)__bfloat16_as_ushort(h0) | ((unsigned)__bfloat16_as_ushort(h1)<<16);
            pl[q] = (unsigned)__bfloat16_as_ushort(l0) | ((unsigned)__bfloat16_as_ushort(l1)<<16);
        }
        uint4* dh = reinterpret_cast<uint4*>(AsH + (buf*128+r)*LDT + hf*16);
        uint4* dl = reinterpret_cast<uint4*>(AsL + (buf*128+r)*LDT + hf*16);
        dh[0] = make_uint4(ph[0],ph[1],ph[2],ph[3]);
        dh[1] = make_uint4(ph[4],ph[5],ph[6],ph[7]);
        dl[0] = make_uint4(pl[0],pl[1],pl[2],pl[3]);
        dl[1] = make_uint4(pl[4],pl[5],pl[6],pl[7]);
    };

    if (MODE==1){ loadA1(0); storeA1(0); } else loadA0(0,0);
    loadB(0,0);
    asm volatile("cp.async.commit_group;");

    for (int ci=0; ci<KCH; ci++){
        int cur = ci & 1, nxt = cur ^ 1;
        if (ci+1 < KCH){
            if (MODE==1) loadA1(ci+1);
            else loadA0(ci+1, nxt);
            loadB(ci+1, nxt);
            asm volatile("cp.async.commit_group;");
            asm volatile("cp.async.wait_group 1;");
        } else {
            asm volatile("cp.async.wait_group 0;");
        }
        __syncthreads();

        const bf* aH = AsH + cur*128*LDT;
        const bf* aL = AsL + cur*128*LDT;
        const bf* bH = BsH + cur*128*LDT;
        const bf* bL = BsL + cur*128*LDT;
#pragma unroll
        for (int ks=0; ks<32; ks+=16){
            unsigned ah[4][4], al[4][4], bb[2][4];
            int arow = wm*64 + (lane&15), acol = ks + ((lane>>4)<<3);
            int brow = wn*32 + ((lane>>4)<<3) + (lane&7), bcol = ks + (((lane>>3)&1)<<3);
#pragma unroll
            for(int mi=0;mi<4;mi++) ldsm4(ah[mi], aH + (arow+mi*16)*LDT + acol);
#pragma unroll
            for(int gi=0;gi<2;gi++) ldsm4(bb[gi], bH + (brow+gi*16)*LDT + bcol);
#pragma unroll
            for(int mi=0;mi<4;mi++)
#pragma unroll
                for(int ni=0;ni<4;ni++)
                    mma16816(c[mi][ni], ah[mi], bb[ni>>1][(ni&1)*2], bb[ni>>1][(ni&1)*2+1]);
#pragma unroll
            for(int mi=0;mi<4;mi++) ldsm4(al[mi], aL + (arow+mi*16)*LDT + acol);
#pragma unroll
            for(int mi=0;mi<4;mi++)
#pragma unroll
                for(int ni=0;ni<4;ni++)
                    mma16816(c[mi][ni], al[mi], bb[ni>>1][(ni&1)*2], bb[ni>>1][(ni&1)*2+1]);
#pragma unroll
            for(int gi=0;gi<2;gi++) ldsm4(bb[gi], bL + (brow+gi*16)*LDT + bcol);
#pragma unroll
            for(int mi=0;mi<4;mi++)
#pragma unroll
                for(int ni=0;ni<4;ni++)
                    mma16816(c[mi][ni], ah[mi], bb[ni>>1][(ni&1)*2], bb[ni>>1][(ni&1)*2+1]);
        }
        if (MODE==1 && ci+1 < KCH) storeA1(nxt);
        __syncthreads();
    }

    // MODE1: wait for theme chain before fused epilogue
    if (MODE==1){
        if (tid==0){
            while (atomicAdd(&g_themeflag, 0u) < 1200u) __nanosleep(128);
        }
        __syncthreads();
        __threadfence();
    }

#pragma unroll
    for(int mi=0;mi<4;mi++){
#pragma unroll
        for(int hf=0; hf<2; hf++){
            int r = m0 + wm*64 + mi*16 + (lane>>2) + hf*8;
#pragma unroll
            for(int ni=0;ni<4;ni++){
                int n = n0 + wn*32 + ni*8 + ((lane&3)<<1);
                float v0 = c[mi][ni][hf*2+0], v1 = c[mi][ni][hf*2+1];
                if (MODE==0){
                    int b = r & 255, v = r >> 8;      // v-major
                    float tval = tv[b*VV + v];
                    size_t base = (size_t)r * GG;
                    if (n < GG)   g_XO[base+n]   = v0 + g_bias[n]   + tval*g_WsumT[n];
                    if (n+1 < GG) g_XO[base+n+1] = v1 + g_bias[n+1] + tval*g_WsumT[n+1];
                } else {
                    int t = r>>8, b = r&255;
                    size_t tb = (size_t)r*HH + n;
                    float o0 = __ldcg(g_theme+tb)  *(v0 + cb[n])   + g_hs[tb];
                    float o1 = __ldcg(g_theme+tb+1)*(v1 + cb[n+1]) + g_hs[tb+1];
                    size_t ob = ((size_t)b*VV + t)*HH + n;
                    g_rnn[ob]   = o0;
                    g_rnn[ob+1] = o1;
                }
            }
        }
    }
    if (MODE==0){
        __threadfence();
        __syncthreads();
        if (tid==0) atomicAdd(&g_vflag[m0>>8], 1u);
    }
}

// ---------------- persistent recurrence: 8 b-groups x cluster-of-8 g-slices ----------------
__global__ void __launch_bounds__(256) __cluster_dims__(8,1,1) k_recur()
{
    extern __shared__ __align__(16) bf rsm[];
    bf* hHs = rsm;
    bf* hLs = hHs + 32*392;
    bf* wHs = hLs + 32*392;
    bf* wLs = wHs + 2*256*LDT;
    uint32_t shH = (uint32_t)__cvta_generic_to_shared(hHs);
    uint32_t shL = (uint32_t)__cvta_generic_to_shared(hLs);
    uint32_t swH = (uint32_t)__cvta_generic_to_shared(wHs);
    uint32_t swL = (uint32_t)__cvta_generic_to_shared(wLs);
    __shared__ float sfm[4][LL], sim[4][LL];

    const int tid = threadIdx.x, lane = tid&31, w = tid>>5;
    const int bgroup = blockIdx.x>>3, rank = blockIdx.x&7;
    const int bbase = bgroup*32;
    const int gg0 = rank*256;

    auto loadH = [&](){
        for (int s=tid; s<3072; s+=256){
            int hl = (s>=1536)?1:0, s2 = s - hl*1536;
            int r = s2/48, seg = s2%48;
            const bf* src = (hl? g_hL : g_hH) + (size_t)(bbase+r)*HH + seg*8;
            uint32_t dst = (hl? shL : shH) + (r*392 + seg*8)*2;
            cpa16(dst, src);
        }
    };
    auto loadW = [&](int ci, int buf){
        for (int s=tid; s<2048; s+=256){
            int hl = s>>10, r = (s&1023)>>2, seg = s&3;
            const bf* src = (hl? g_WrL : g_WrH) + (size_t)(gg0+r)*HH + ci*32 + seg*8;
            uint32_t dst = (hl? swL : swH) + ((buf*256+r)*LDT + seg*8)*2;
            cpa16(dst, src);
        }
    };

    for (int t=0; t<VV; t++){
        float c[2][4][4];
#pragma unroll
        for(int a=0;a<2;a++)
#pragma unroll
            for(int b=0;b<4;b++)
#pragma unroll
                for(int q=0;q<4;q++) c[a][b][q]=0.f;

        loadH(); loadW(0,0);
        asm volatile("cp.async.commit_group;");
        asm volatile("cp.async.wait_group 0;");
        __syncthreads();

        for (int ci=0; ci<12; ci++){
            int cur = ci&1;
            if (ci+1 < 12){
                loadW(ci+1, cur^1);
                asm volatile("cp.async.commit_group;");
                asm volatile("cp.async.wait_group 1;");
            } else {
                asm volatile("cp.async.wait_group 0;");
            }
            __syncthreads();
#pragma unroll
            for (int ks=0; ks<32; ks+=16){
                unsigned ah[2][4], al[2][4], bb[2][4];
                int arow = lane&15, acol = ci*32 + ks + ((lane>>4)<<3);
                int brow = w*32 + ((lane>>4)<<3) + (lane&7), bcol = ks + (((lane>>3)&1)<<3);
#pragma unroll
                for(int mi=0;mi<2;mi++) ldsm4(ah[mi], hHs + (arow+mi*16)*392 + acol);
#pragma unroll
                for(int gi=0;gi<2;gi++) ldsm4(bb[gi], wHs + (cur*256+brow+gi*16)*LDT + bcol);
#pragma unroll
                for(int mi=0;mi<2;mi++)
#pragma unroll
                    for(int ni=0;ni<4;ni++)
                        mma16816(c[mi][ni], ah[mi], bb[ni>>1][(ni&1)*2], bb[ni>>1][(ni&1)*2+1]);
#pragma unroll
                for(int mi=0;mi<2;mi++) ldsm4(al[mi], hLs + (arow+mi*16)*392 + acol);
#pragma unroll
                for(int mi=0;mi<2;mi++)
#pragma unroll
                    for(int ni=0;ni<4;ni++)
                        mma16816(c[mi][ni], al[mi], bb[ni>>1][(ni&1)*2], bb[ni>>1][(ni&1)*2+1]);
#pragma unroll
                for(int gi=0;gi<2;gi++) ldsm4(bb[gi], wLs + (cur*256+brow+gi*16)*LDT + bcol);
#pragma unroll
                for(int mi=0;mi<2;mi++)
#pragma unroll
                    for(int ni=0;ni<4;ni++)
                        mma16816(c[mi][ni], ah[mi], bb[ni>>1][(ni&1)*2], bb[ni>>1][(ni&1)*2+1]);
            }
            __syncthreads();
        }

        // wait for XO[t] readiness from overlapped k_gma<0>
        if (tid==0){
            while (atomicAdd(&g_vflag[t], 0u) < 26u) __nanosleep(128);
        }
        __syncthreads();
        __threadfence();

        // epilogue: xo = c + XO[t]
#pragma unroll
        for(int mi=0;mi<2;mi++){
#pragma unroll
            for(int hf=0; hf<2; hf++){
                int rloc = mi*16 + (lane>>2) + hf*8;
                int b = bbase + rloc;
                size_t xbase = ((size_t)t*BB + b)*GG;
#pragma unroll
                for(int ni=0;ni<4;ni++){
                    int g = gg0 + w*32 + ni*8 + ((lane&3)<<1);
                    if (g < GG)   g_xobuf[(size_t)b*GG+g]   = c[mi][ni][hf*2+0] + __ldcg(g_XO+xbase+g);
                    if (g+1 < GG) g_xobuf[(size_t)b*GG+g+1] = c[mi][ni][hf*2+1] + __ldcg(g_XO+xbase+g+1);
                }
            }
        }
        __threadfence();
        asm volatile("barrier.cluster.arrive.aligned;" ::: "memory");
        asm volatile("barrier.cluster.wait.aligned;" ::: "memory");

        // ---- phase B: 4 b per CTA ----
        {
            int b_local = w>>1, half = w&1;
            int b = bbase + rank*4 + b_local;
            const float* xo = g_xobuf + (size_t)b*GG;
            if (half==0 && lane==0){
                float v[LL], mx=-1e30f;
#pragma unroll
                for(int i=0;i<LL;i++){ v[i]=__ldcg(xo+i); mx=fmaxf(mx,v[i]); }
                float s=0.f;
#pragma unroll
                for(int i=0;i<LL;i++){ v[i]=expf(v[i]-mx); s+=v[i]; }
                float inv=1.f/s, run=0.f, fsum=0.f;
#pragma unroll
                for(int i=0;i<LL;i++){ run+=v[i]*inv; sfm[b_local][i]=run; fsum+=run; }
                g_dists[t*BB+b] = 1.f - fsum/(float)LL;
            } else if (half==0 && lane==16){
                float v[LL], mx=-1e30f;
#pragma unroll
                for(int i=0;i<LL;i++){ v[i]=__ldcg(xo+LL+i); mx=fmaxf(mx,v[i]); }
                float s=0.f;
#pragma unroll
                for(int i=0;i<LL;i++){ v[i]=expf(v[i]-mx); s+=v[i]; }
                float inv=1.f/s, run=0.f;
#pragma unroll
                for(int i=LL-1;i>=0;i--){ run+=v[i]*inv; sim[b_local][i]=run; }
            }
            __syncthreads();
#pragma unroll
            for(int r=0;r<6;r++){
                int hh = half*192 + r*32 + lane;
                int l = hh>>5;
                float fg = sigmoidf(__ldcg(xo+24+hh));
                float ig = sigmoidf(__ldcg(xo+24+384+hh));
                float og = sigmoidf(__ldcg(xo+24+768+hh));
                float ci = tanhf(__ldcg(xo+24+1152+hh));
                float fmv=sfm[b_local][l], imv=sim[b_local][l], ov=fmv*imv;
                float cold = g_c[b*HH+hh];
                float cn = ov*(fg*cold+ig*ci) + (fmv-ov)*cold + (imv-ov)*ci;
                float hv = og*tanhf(cn);
                g_c[b*HH+hh]=cn;
                bsplit(hv, g_hH[b*HH+hh], g_hL[b*HH+hh]);
                g_hs[((size_t)t*BB+b)*HH+hh]=hv;
            }
        }
        __threadfence();
        asm volatile("barrier.cluster.arrive.aligned;" ::: "memory");
        asm volatile("barrier.cluster.wait.aligned;" ::: "memory");
    }
}

// ---------------- fp32 64x64 NT tile helper ----------------
__device__ __forceinline__ void gemm64(const float* __restrict__ A, int lda,
                                       const float* __restrict__ Bm, int ldb,
                                       int K, int brows, float (&acc)[4][4],
                                       float* As, float* Bs)
{
    int tid=threadIdx.x, lrow=tid>>2, lcol=(tid&3)<<2, trow=tid>>4, tcol=tid&15;
    for (int k0=0;k0<K;k0+=16){
        float4 a4 = *reinterpret_cast<const float4*>(A + (size_t)lrow*lda + k0 + lcol);
        float4 b4 = make_float4(0.f,0.f,0.f,0.f);
        if (lrow < brows) b4 = *reinterpret_cast<const float4*>(Bm + (size_t)lrow*ldb + k0 + lcol);
        As[(lcol+0)*64+lrow]=a4.x; As[(lcol+1)*64+lrow]=a4.y;
        As[(lcol+2)*64+lrow]=a4.z; As[(lcol+3)*64+lrow]=a4.w;
        Bs[(lcol+0)*64+lrow]=b4.x; Bs[(lcol+1)*64+lrow]=b4.y;
        Bs[(lcol+2)*64+lrow]=b4.z; Bs[(lcol+3)*64+lrow]=b4.w;
        __syncthreads();
#pragma unroll
        for (int p=0;p<16;p++){
            float ar[4], br[4];
#pragma unroll
            for(int i=0;i<4;i++) ar[i]=As[p*64+trow*4+i];
#pragma unroll
            for(int j=0;j<4;j++) br[j]=Bs[p*64+tcol*4+j];
#pragma unroll
            for(int i=0;i<4;i++)
#pragma unroll
                for(int j=0;j<4;j++) acc[i][j]=fmaf(ar[i],br[j],acc[i][j]);
        }
        __syncthreads();
    }
}

// ---------------- ld weights ----------------
__global__ void k_ld()
{
    int idx = blockIdx.x*256 + threadIdx.x;
    int t = idx/BB, b = idx%BB;
    float cum[CSS], run=0.f;
#pragma unroll
    for(int k=0;k<CSS;k++){
        int s = t-(CSS-1)+k;
        run += (s>=0)? g_dists[s*BB+b] : 0.f;
        cum[k]=run;
    }
    float mx=cum[0];
#pragma unroll
    for(int k=1;k<CSS;k++) mx=fmaxf(mx,cum[k]);
    float e[CSS], s=0.f;
#pragma unroll
    for(int k=0;k<CSS;k++){ e[k]=expf(cum[k]-mx); s+=e[k]; }
    float inv=1.f/s;
#pragma unroll
    for(int k=0;k<CSS;k++) g_ld[(size_t)idx*CSS+k]=e[k]*inv;
}

// ---------------- mh = mean_k ld*hs ----------------
__global__ void k_mh()
{
    long idx = (long)blockIdx.x*256 + threadIdx.x;
    int t = (int)(idx/(BB*HH));
    int r = (int)(idx%(BB*HH));
    int b = r/HH, h = r%HH;
    const float* ld = g_ld + ((size_t)t*BB+b)*CSS;
    float s=0.f;
#pragma unroll
    for(int k=0;k<CSS;k++){
        int sv = t-(CSS-1)+k;
        if (sv>=0) s += ld[k]*g_hs[((size_t)sv*BB+b)*HH+h];
    }
    g_mh[idx] = s*0.1f;
}

// ---------------- theme MLP ----------------
__global__ void __launch_bounds__(256) k_theme1(const float* __restrict__ sw, const float* __restrict__ sb)
{
    __shared__ float As[16*64], Bs[16*64];
    int m0 = blockIdx.y*64;
    float acc[4][4] = {};
    gemm64(g_mh + (size_t)m0*HH, HH, sw, HH, HH, 64, acc, As, Bs);
    int trow=threadIdx.x>>4, tcol=threadIdx.x&15;
#pragma unroll
    for(int i=0;i<4;i++){
        int m=m0+trow*4+i;
#pragma unroll
        for(int j=0;j<4;j++){
            int n=tcol*4+j;
            g_hid[(size_t)m*HSS+n] = fmaxf(acc[i][j]+sb[n], 0.f);
        }
    }
}
__global__ void __launch_bounds__(256) k_theme2(const float* __restrict__ rsw, const float* __restrict__ rsb)
{
    __shared__ float As[16*64], Bs[16*64];
    int n0 = blockIdx.x*64, m0 = blockIdx.y*64;
    float acc[4][4] = {};
    gemm64(g_hid + (size_t)m0*HSS, HSS, rsw + (size_t)n0*HSS, HSS, HSS, 64, acc, As, Bs);
    int trow=threadIdx.x>>4, tcol=threadIdx.x&15;
#pragma unroll
    for(int i=0;i<4;i++){
        int m=m0+trow*4+i;
#pragma unroll
        for(int j=0;j<4;j++){
            int n=n0+tcol*4+j;
            g_theme[(size_t)m*HH+n] = sigmoidf(acc[i][j]+rsb[n]);
        }
    }
    __threadfence();
    __syncthreads();
    if (threadIdx.x==0) atomicAdd(&g_themeflag, 1u);
}

// ---------------- out GEMM (split-K) + reduce ----------------
__global__ void __launch_bounds__(256) k_out(const float* __restrict__ ow)
{
    __shared__ float As[16*64], Bs[16*64];
    int n0=blockIdx.x*64, m0=blockIdx.y*64, z=blockIdx.z;
    float acc[4][4] = {};
    gemm64(g_rnn + (size_t)m0*(VV*HH) + z*1200, VV*HH,
           ow + (size_t)n0*(VV*HH) + z*1200, VV*HH, 1200, 64, acc, As, Bs);
    int trow=threadIdx.x>>4, tcol=threadIdx.x&15;
#pragma unroll
    for(int i=0;i<4;i++){
        int m=m0+trow*4+i;
#pragma unroll
        for(int j=0;j<4;j++){
            int n=n0+tcol*4+j;
            g_outPart[((size_t)z*BB+m)*OUTT+n]=acc[i][j];
        }
    }
}
__global__ void k_reduce(const float* __restrict__ out_b, float* __restrict__ outp, int total)
{
    int idx = blockIdx.x*256 + threadIdx.x;
    if (idx >= total) return;
    if (idx < BB*OUTT){
        float s = out_b[idx & (OUTT-1)];
#pragma unroll
        for(int z=0;z<16;z++) s += g_outPart[(size_t)z*(BB*OUTT)+idx];
        outp[idx]=s;
    } else if (idx < BB*OUTT + VV*BB){
        outp[idx] = g_dists[idx - BB*OUTT];
    }
}

// ---------------- launch ----------------
extern "C" void kernel_launch(void* const* d_in, const int* in_sizes, int n_in,
                              void* d_out, int out_size)
{
    const int*   node_ids  = (const int*)d_in[0];
    const float* timev     = (const float*)d_in[3];
    const float* embed     = (const float*)d_in[6];
    const float* kernel_w  = (const float*)d_in[7];
    const float* kernel_b  = (const float*)d_in[8];
    const float* rec_w     = (const float*)d_in[9];
    const float* rec_b     = (const float*)d_in[10];
    const float* scale_w   = (const float*)d_in[11];
    const float* scale_b   = (const float*)d_in[12];
    const float* rescale_w = (const float*)d_in[13];
    const float* rescale_b = (const float*)d_in[14];
    const float* conv_w    = (const float*)d_in[15];
    const float* conv_b    = (const float*)d_in[16];
    const float* out_w     = (const float*)d_in[17];
    const float* out_b     = (const float*)d_in[18];
    float* outp = (float*)d_out;

    const int SMEM = 2*128*LDT*2*4;                       // 81920
    const int SMEM_R = (2*32*392 + 2*2*256*LDT)*2;        // 132096
    static bool cfg = false;
    static cudaStream_t s1 = 0;
    static cudaEvent_t evA, evB, evC, evD;
    if (!cfg){
        cudaFuncSetAttribute(k_gma<0>, cudaFuncAttributeMaxDynamicSharedMemorySize, SMEM);
        cudaFuncSetAttribute(k_gma<1>, cudaFuncAttributeMaxDynamicSharedMemorySize, SMEM);
        cudaFuncSetAttribute(k_recur, cudaFuncAttributeMaxDynamicSharedMemorySize, SMEM_R);
        cudaStreamCreateWithFlags(&s1, cudaStreamNonBlocking);
        cudaEventCreateWithFlags(&evA, cudaEventDisableTiming);
        cudaEventCreateWithFlags(&evB, cudaEventDisableTiming);
        cudaEventCreateWithFlags(&evC, cudaEventDisableTiming);
        cudaEventCreateWithFlags(&evD, cudaEventDisableTiming);
        cfg = true;
    }

    long prep_total = (long)GPAD*NDI + 10001L*DD + (long)HH*KC2 + GG + (long)GP2*HH + (long)BB*HH + VV + 1;
    k_prep<<<(int)((prep_total+255)/256), 256>>>(kernel_w, rec_w, conv_w, kernel_b, rec_b, embed);

    // fork: recur on s1 (launched first so its CTAs get resident), gma0 on default stream
    cudaEventRecord(evA, 0);
    cudaStreamWaitEvent(s1, evA, 0);
    k_recur<<<64, 256, SMEM_R, s1>>>();
    k_gma<0><<<dim3(13,100), 256, SMEM>>>(node_ids, timev, conv_b);

    // join recur, then ld
    cudaEventRecord(evB, s1);
    cudaStreamWaitEvent(0, evB, 0);
    k_ld<<<50, 256>>>();

    // fork: gma1 on s1 (epilogue spins on themeflag); theme chain on default stream
    cudaEventRecord(evC, 0);
    cudaStreamWaitEvent(s1, evC, 0);
    k_gma<1><<<dim3(3,100), 256, SMEM, s1>>>(node_ids, timev, conv_b);
    cudaEventRecord(evD, s1);
    k_mh<<<19200, 256>>>();
    k_theme1<<<dim3(1,200), 256>>>(scale_w, scale_b);
    k_theme2<<<dim3(6,200), 256>>>(rescale_w, rescale_b);

    // join gma1, then out + reduce
    cudaStreamWaitEvent(0, evD, 0);
    k_out<<<dim3(2,4,16), 256>>>(out_w);
    k_reduce<<<(out_size+255)/256, 256>>>(out_b, outp, out_size);
}